// round 2
// baseline (speedup 1.0000x reference)
#include <cuda_runtime.h>

#define D 32
#define NMID 80

// Scratch (no allocations allowed): composed affine map + control.
__device__ float gA[D * D];       // composed matrix, row-major [out][in]
__device__ float gC[D];           // composed bias
__device__ float gColMax[D];      // per-column max |A|
__device__ int   gFlag;           // 1 => A negligible, broadcast c
__device__ unsigned int gCtr = 0; // last-block-done counter (self-resetting)

// ---------------------------------------------------------------------------
// K1: compose the 82 affine layers into (A, c).
// Grid: 33 blocks x 32 threads. Block j in [0,32) scans column j of A;
// block 32 scans the bias vector c. Lane m holds element m of the vector.
// Step: v'[i] = sum_m W[i][m] * v[m]  (lane i: 8x LDG.128 of its W row,
// 32 shfl broadcasts of v, 32 FMAs into 4 partial accumulators).
// ---------------------------------------------------------------------------
__global__ void compose_kernel(const float* __restrict__ W1,
                               const float* __restrict__ b1,
                               const float* __restrict__ Wm,
                               const float* __restrict__ bm,
                               const float* __restrict__ W6,
                               const float* __restrict__ b6) {
    const int j    = blockIdx.x;   // 0..31 => column j of A, 32 => bias scan
    const int lane = threadIdx.x;  // 0..31
    const bool isC = (j == D);

    float v = isC ? b1[lane] : W1[lane * D + j];

    float w[D];
#pragma unroll 1
    for (int k = 0; k <= NMID; ++k) {
        const float* W = (k < NMID) ? (Wm + (size_t)k * D * D) : W6;

        // Load my row of W (row 'lane'): 8 x float4.
        const float4* wr = (const float4*)(W + lane * D);
#pragma unroll
        for (int q = 0; q < 8; ++q) ((float4*)w)[q] = wr[q];

        float a0 = 0.f, a1 = 0.f, a2 = 0.f, a3 = 0.f;
#pragma unroll
        for (int m = 0; m < D; m += 4) {
            float v0 = __shfl_sync(0xffffffffu, v, m + 0);
            float v1 = __shfl_sync(0xffffffffu, v, m + 1);
            float v2 = __shfl_sync(0xffffffffu, v, m + 2);
            float v3 = __shfl_sync(0xffffffffu, v, m + 3);
            a0 = fmaf(w[m + 0], v0, a0);
            a1 = fmaf(w[m + 1], v1, a1);
            a2 = fmaf(w[m + 2], v2, a2);
            a3 = fmaf(w[m + 3], v3, a3);
        }
        v = (a0 + a1) + (a2 + a3);
        if (isC) {
            const float* b = (k < NMID) ? (bm + (size_t)k * D) : b6;
            v += b[lane];
        }
    }

    if (isC) {
        gC[lane] = v;
    } else {
        gA[lane * D + j] = v;
        float a = fabsf(v);
#pragma unroll
        for (int o = 16; o > 0; o >>= 1)
            a = fmaxf(a, __shfl_xor_sync(0xffffffffu, a, o));
        if (lane == 0) gColMax[j] = a;
    }

    // Last-block-done: compute flag after all 33 blocks stored their results.
    __threadfence();
    __syncwarp();
    if (lane == 0) {
        unsigned t = atomicAdd(&gCtr, 1u);
        if (t == 32u) {            // I'm the 33rd (last) block
            __threadfence();       // acquire the other blocks' stores
            float amax = 0.f;
#pragma unroll
            for (int q = 0; q < D; ++q) amax = fmaxf(amax, gColMax[q]);
            gFlag = (amax < 1e-12f) ? 1 : 0;
            gCtr = 0;              // reset for next graph replay
            __threadfence();
        }
    }
}

// ---------------------------------------------------------------------------
// K2: produce the output.
// Fast path (A negligible): out[b][:] = c for every row -> pure 128MB
// write stream of the repeating 128B pattern. Each thread owns ONE fixed
// float4 slot of the pattern (total threads % 8 == 0), so the loop body is
// just STG.128.
// Fallback: out[b][i] = c[i] + sum_j A[i][j] * x[b][j] (correct, slower).
// ---------------------------------------------------------------------------
__global__ void output_kernel(const float* __restrict__ x,
                              float* __restrict__ out,
                              int n4 /* out_size / 4 */) {
    const int tid = blockIdx.x * blockDim.x + threadIdx.x;
    const int nt  = gridDim.x * blockDim.x;   // multiple of 8 by construction
    const int flag = gFlag;                   // uniform across grid

    if (flag) {
        const float4 cv = ((const float4*)gC)[tid & 7];
        float4* o4 = (float4*)out;
        for (int i = tid; i < n4; i += nt) o4[i] = cv;
    } else {
        float Ar[D];  // not enough regs for all of A per thread; element map
        (void)Ar;
        const int n = n4 * 4;
        for (int e = tid; e < n; e += nt) {
            const int b = e >> 5;
            const int i = e & 31;
            const float* xr = x + (size_t)b * D;
            float acc = gC[i];
#pragma unroll
            for (int jj = 0; jj < D; ++jj)
                acc = fmaf(gA[i * D + jj], xr[jj], acc);
            out[e] = acc;
        }
    }
}

// ---------------------------------------------------------------------------
// Launch. Inputs (metadata order): x, W1, b1, Wm, bm, W6, b6 — identified
// robustly by element counts (relative order disambiguates W1/W6, b1/b6).
// ---------------------------------------------------------------------------
extern "C" void kernel_launch(void* const* d_in, const int* in_sizes, int n_in,
                              void* d_out, int out_size) {
    const float *x = 0, *W1 = 0, *b1 = 0, *Wm = 0, *bm = 0, *W6 = 0, *b6 = 0;
    for (int i = 0; i < n_in; ++i) {
        const int s = in_sizes[i];
        const float* p = (const float*)d_in[i];
        if (s > 100000) {
            if (s == NMID * D * D) Wm = p; else x = p;
        } else if (s == NMID * D * D) {
            Wm = p;
        } else if (s == NMID * D) {
            bm = p;
        } else if (s == D * D) {
            if (!W1) W1 = p; else W6 = p;
        } else if (s == D) {
            if (!b1) b1 = p; else b6 = p;
        }
    }

    compose_kernel<<<33, 32>>>(W1, b1, Wm, bm, W6, b6);

    const int n4 = out_size / 4;
    // 1184 blocks x 256 threads = 303104 threads (multiple of 8), ~8 blocks/SM.
    output_kernel<<<1184, 256>>>(x, (float*)d_out, n4);
}

// round 3
// speedup vs baseline: 1.7136x; 1.7136x over previous
#include <cuda_runtime.h>

#define D 32
#define NMID 80
#define NLAY 82          // total layers
#define AD 33            // augmented dim
#define ST 36            // padded row stride (floats)
#define MSZ (AD * ST)    // 1188 floats per matrix
#define NB 41            // compose blocks (<= SM count => co-resident)
#define NT 320           // compose threads per block

// Global scratch (no allocations allowed).
__device__ __align__(16) float gM0[NB * MSZ];
__device__ __align__(16) float gM1[NB * MSZ];
__device__ int gFlag;                 // 1 => composed A negligible
__device__ unsigned gCount = 0;       // barrier arrive counter (self-reset)
__device__ volatile unsigned gPhase = 0;  // monotone barrier phase (replay-safe)

// ---------------------------------------------------------------------------
// Software grid barrier. All NB blocks are resident (grid <= #SMs), so a
// spin barrier is safe. gPhase grows monotonically across graph replays;
// each kernel instance captures `base` at entry (all blocks read the same
// value: phase can't advance until every block has arrived at barrier 1,
// which happens after every block read base).
// ---------------------------------------------------------------------------
__device__ __forceinline__ void grid_barrier(unsigned base, int it) {
    __syncthreads();
    if (threadIdx.x == 0) {
        __threadfence();                      // release my block's stores
        unsigned c = atomicAdd(&gCount, 1u);
        if (c == NB - 1u) {
            gCount = 0u;
            __threadfence();
            gPhase = gPhase + 1u;             // single writer: last arriver
        } else {
            while (gPhase < base + (unsigned)it) { }
        }
        __threadfence();                      // acquire other blocks' stores
    }
    __syncthreads();
}

// Build augmented matrix for layer l into smem S [AD x ST].
__device__ __forceinline__ void load_aug(float* S, int l,
                                         const float* __restrict__ W1,
                                         const float* __restrict__ b1,
                                         const float* __restrict__ Wm,
                                         const float* __restrict__ bm,
                                         const float* __restrict__ W6,
                                         const float* __restrict__ b6) {
    const float* W;
    const float* b;
    if (l == 0)            { W = W1; b = b1; }
    else if (l == NLAY - 1){ W = W6; b = b6; }
    else                   { W = Wm + (size_t)(l - 1) * D * D; b = bm + (l - 1) * D; }
    for (int i = threadIdx.x; i < MSZ; i += NT) {
        int r = i / ST, c = i % ST;
        float v = 0.f;
        if (r < D && c < D)            v = W[r * D + c];
        else if (r < D && c == D)      v = b[r];
        else if (r == D && c == D)     v = 1.f;
        S[i] = v;
    }
}

// Copy a matrix (global, 16B aligned) into smem.
__device__ __forceinline__ void load_mat(float* S, const float* g) {
    const float4* g4 = (const float4*)g;
    float4* s4 = (float4*)S;
    for (int i = threadIdx.x; i < MSZ / 4; i += NT) s4[i] = g4[i];
}

// C = L * R, all AD x AD (padded to ST). L,R in smem; C to global.
// Thread t < 297: row r = t/9, column group g = t%9 (4 cols each, 36 total;
// padding cols stay zero because R's padding cols are zero).
__device__ __forceinline__ void mm(const float* __restrict__ Ls,
                                   const float* __restrict__ Rs,
                                   float* __restrict__ out) {
    int t = threadIdx.x;
    if (t < (AD * ST) / 4) {       // 297
        int r = t / 9, g = t % 9;
        float a0 = 0.f, a1 = 0.f, a2 = 0.f, a3 = 0.f;
#pragma unroll
        for (int k = 0; k < AD; ++k) {
            float l = Ls[r * ST + k];
            float4 rv = *(const float4*)&Rs[k * ST + g * 4];
            a0 = fmaf(l, rv.x, a0);
            a1 = fmaf(l, rv.y, a1);
            a2 = fmaf(l, rv.z, a2);
            a3 = fmaf(l, rv.w, a3);
        }
        float4 o = make_float4(a0, a1, a2, a3);
        *(float4*)&out[r * ST + g * 4] = o;
    }
}

// ---------------------------------------------------------------------------
// K1: tree-compose the 82 augmented layers. 41 blocks, 7 levels, grid
// barriers between levels. Final product lands in gM0[0].
// ---------------------------------------------------------------------------
__global__ void __launch_bounds__(NT)
compose_tree_kernel(const float* __restrict__ W1, const float* __restrict__ b1,
                    const float* __restrict__ Wm, const float* __restrict__ bm,
                    const float* __restrict__ W6, const float* __restrict__ b6) {
    __shared__ __align__(16) float Ls[MSZ];
    __shared__ __align__(16) float Rs[MSZ];
    const unsigned base = gPhase;       // entry phase (same for all blocks)
    const int k = blockIdx.x;
    int it = 0;

    // Level 1: pair adjacent layers. Block k: out = M[2k+1] * M[2k].
    load_aug(Rs, 2 * k,     W1, b1, Wm, bm, W6, b6);
    load_aug(Ls, 2 * k + 1, W1, b1, Wm, bm, W6, b6);
    __syncthreads();
    mm(Ls, Rs, gM0 + (size_t)k * MSZ);
    grid_barrier(base, ++it);

    // Tree levels: 41 -> 21 -> 11 -> 6 -> 3 -> 2 -> 1
    float* bufs[2] = { gM0, gM1 };
    int cur = 0;
    int n = NB;
    while (n > 1) {
        int nn = (n + 1) >> 1;
        if (k < nn) {
            const float* in  = bufs[cur];
            float*       out = bufs[cur ^ 1];
            if (2 * k + 1 < n) {
                load_mat(Rs, in + (size_t)(2 * k)     * MSZ);
                load_mat(Ls, in + (size_t)(2 * k + 1) * MSZ);
                __syncthreads();
                mm(Ls, Rs, out + (size_t)k * MSZ);
            } else {
                // odd leftover: pass through
                const float4* s = (const float4*)(in + (size_t)(2 * k) * MSZ);
                float4* d = (float4*)(out + (size_t)k * MSZ);
                for (int i = threadIdx.x; i < MSZ / 4; i += NT) d[i] = s[i];
            }
        }
        cur ^= 1;
        n = nn;
        grid_barrier(base, ++it);
    }
    // 6 swaps from gM0 => final result is back in gM0[0].

    // Block 0: decide broadcast flag from max|A|.
    if (k == 0) {
        __shared__ int samax;
        if (threadIdx.x == 0) samax = 0;
        __syncthreads();
        float m = 0.f;
        for (int i = threadIdx.x; i < MSZ; i += NT) {
            int r = i / ST, c = i % ST;
            if (r < D && c < D) m = fmaxf(m, fabsf(gM0[i]));
        }
        atomicMax(&samax, __float_as_int(m));  // nonneg floats: int order ok
        __syncthreads();
        if (threadIdx.x == 0)
            gFlag = (__int_as_float(samax) < 1e-12f) ? 1 : 0;
    }
}

// ---------------------------------------------------------------------------
// K2: produce the output.
// Fast path (A negligible): out[b][:] = c — pure 128MB streaming-write of
// the repeating 128B pattern (thread owns one fixed float4 slot).
// Fallback: out[b][i] = c[i] + sum_j A[i][j] * x[b][j]  (always correct).
// Final composed matrix lives in gM0[0] with row stride ST; c is column 32.
// ---------------------------------------------------------------------------
__global__ void output_kernel(const float* __restrict__ x,
                              float* __restrict__ out,
                              int n4 /* out_size / 4 */) {
    const int tid = blockIdx.x * blockDim.x + threadIdx.x;
    const int nt  = gridDim.x * blockDim.x;   // multiple of 8 by construction
    const int flag = gFlag;

    if (flag) {
        const int slot = tid & 7;             // which float4 of the 128B row
        float4 cv = make_float4(gM0[(slot * 4 + 0) * ST + D],
                                gM0[(slot * 4 + 1) * ST + D],
                                gM0[(slot * 4 + 2) * ST + D],
                                gM0[(slot * 4 + 3) * ST + D]);
        float4* o4 = (float4*)out;
        for (int i = tid; i < n4; i += nt) __stcs(&o4[i], cv);
    } else {
        const int n = n4 * 4;
        for (int e = tid; e < n; e += nt) {
            const int b = e >> 5;
            const int i = e & 31;
            const float* xr = x + (size_t)b * D;
            float acc = gM0[i * ST + D];          // c[i]
#pragma unroll
            for (int jj = 0; jj < D; ++jj)
                acc = fmaf(gM0[i * ST + jj], xr[jj], acc);
            out[e] = acc;
        }
    }
}

// ---------------------------------------------------------------------------
// Launch. Inputs identified robustly by element counts (relative order
// disambiguates W1/W6 and b1/b6).
// ---------------------------------------------------------------------------
extern "C" void kernel_launch(void* const* d_in, const int* in_sizes, int n_in,
                              void* d_out, int out_size) {
    const float *x = 0, *W1 = 0, *b1 = 0, *Wm = 0, *bm = 0, *W6 = 0, *b6 = 0;
    for (int i = 0; i < n_in; ++i) {
        const int s = in_sizes[i];
        const float* p = (const float*)d_in[i];
        if (s == NMID * D * D) {
            Wm = p;
        } else if (s > 100000) {
            x = p;
        } else if (s == NMID * D) {
            bm = p;
        } else if (s == D * D) {
            if (!W1) W1 = p; else W6 = p;
        } else if (s == D) {
            if (!b1) b1 = p; else b6 = p;
        }
    }

    compose_tree_kernel<<<NB, NT>>>(W1, b1, Wm, bm, W6, b6);

    const int n4 = out_size / 4;
    output_kernel<<<1184, 256>>>(x, (float*)d_out, n4);
}

// round 4
// speedup vs baseline: 1.7692x; 1.0325x over previous
#include <cuda_runtime.h>

#define D 32
#define NMID 80
#define NLAY 82          // total layers
#define AD 33            // augmented dim
#define ST 36            // padded row stride (floats)
#define MSZ (AD * ST)    // 1188 floats per matrix
#define NBA 14           // phase-A blocks
#define CH  6            // layers per phase-A block (last gets 4)
#define NBB 4            // phase-B blocks
#define CHB 4            // partials per phase-B block (last gets 2)
#define NT  320          // threads per block

// Global scratch (no allocations allowed).
__device__ __align__(16) float gP[NBA * MSZ];   // phase-A partial products
__device__ __align__(16) float gQ[NBB * MSZ];   // phase-B partial products
__device__ __align__(16) float gF[MSZ];         // final composed (A|c)
__device__ int gFlag;                           // 1 => A negligible
__device__ unsigned gCount = 0;                 // barrier counter (self-reset)
__device__ volatile unsigned gPhase = 0;        // monotone phase (replay-safe)

// ---------------------------------------------------------------------------
// Software grid barrier with backoff. NBA blocks <= SM count => co-resident.
// gPhase is monotone across graph replays; `base` is captured at entry (all
// blocks read it before any block can complete barrier 1).
// ---------------------------------------------------------------------------
__device__ __forceinline__ void grid_barrier(unsigned base, int it) {
    __syncthreads();
    if (threadIdx.x == 0) {
        __threadfence();
        unsigned c = atomicAdd(&gCount, 1u);
        if (c == NBA - 1u) {
            gCount = 0u;
            __threadfence();
            gPhase = gPhase + 1u;          // single writer (last arriver)
        } else {
            const unsigned tgt = base + (unsigned)it;
            while (gPhase < tgt) { __nanosleep(64); }
        }
        __threadfence();
    }
    __syncthreads();
}

// Build augmented matrix for layer l into smem S [AD x ST].
__device__ __forceinline__ void load_aug(float* S, int l,
                                         const float* __restrict__ W1,
                                         const float* __restrict__ b1,
                                         const float* __restrict__ Wm,
                                         const float* __restrict__ bm,
                                         const float* __restrict__ W6,
                                         const float* __restrict__ b6) {
    const float* W;
    const float* b;
    if (l == 0)             { W = W1; b = b1; }
    else if (l == NLAY - 1) { W = W6; b = b6; }
    else { W = Wm + (size_t)(l - 1) * D * D; b = bm + (l - 1) * D; }
    for (int i = threadIdx.x; i < MSZ; i += NT) {
        int r = i / ST, c = i % ST;
        float v = 0.f;
        if (r < D && c < D)        v = W[r * D + c];
        else if (r < D && c == D)  v = b[r];
        else if (r == D && c == D) v = 1.f;
        S[i] = v;
    }
}

// Copy a matrix (16B-aligned) global -> smem.
__device__ __forceinline__ void load_mat(float* S, const float* g) {
    const float4* g4 = (const float4*)g;
    float4* s4 = (float4*)S;
    for (int i = threadIdx.x; i < MSZ / 4; i += NT) s4[i] = g4[i];
}

// Copy smem -> global.
__device__ __forceinline__ void store_mat(float* g, const float* S) {
    const float4* s4 = (const float4*)S;
    float4* g4 = (float4*)g;
    for (int i = threadIdx.x; i < MSZ / 4; i += NT) g4[i] = s4[i];
}

// out = L * R  (all AD x AD padded to ST). 297 active threads:
// thread t: row r = t/9, col group g = t%9 (4 cols). Padding cols of R are
// zero so padding of out stays zero.
__device__ __forceinline__ void mm(const float* __restrict__ Ls,
                                   const float* __restrict__ Rs,
                                   float* __restrict__ out) {
    int t = threadIdx.x;
    if (t < (AD * ST) / 4) {   // 297
        int r = t / 9, g = t % 9;
        float a0 = 0.f, a1 = 0.f, a2 = 0.f, a3 = 0.f;
#pragma unroll
        for (int k = 0; k < AD; ++k) {
            float l = Ls[r * ST + k];
            float4 rv = *(const float4*)&Rs[k * ST + g * 4];
            a0 = fmaf(l, rv.x, a0);
            a1 = fmaf(l, rv.y, a1);
            a2 = fmaf(l, rv.z, a2);
            a3 = fmaf(l, rv.w, a3);
        }
        *(float4*)&out[r * ST + g * 4] = make_float4(a0, a1, a2, a3);
    }
}

// ---------------------------------------------------------------------------
// Compose the 82 augmented layers into gF with only 2 grid barriers.
// Full product = M81 * ... * M0. Phase A: block k owns layers
// [k*CH, min(82,(k+1)*CH)) and computes their ordered product serially in
// smem. Phase B: 4 blocks combine the 14 partials. Phase C: block 0 combines
// the 4 results, writes gF and gFlag.
// ---------------------------------------------------------------------------
__global__ void __launch_bounds__(NT)
compose_kernel(const float* __restrict__ W1, const float* __restrict__ b1,
               const float* __restrict__ Wm, const float* __restrict__ bm,
               const float* __restrict__ W6, const float* __restrict__ b6) {
    __shared__ __align__(16) float WB[CH][MSZ];   // 28.5 KB
    __shared__ __align__(16) float ACC[2][MSZ];   //  9.5 KB
    const unsigned base = gPhase;
    const int k = blockIdx.x;

    // ---- Phase A ----
    {
        const int lo = k * CH;
        const int hi = (lo + CH < NLAY) ? lo + CH : NLAY;
        const int n  = hi - lo;                    // 6 (or 4 for last block)
        for (int i = 0; i < n; ++i)
            load_aug(WB[i], lo + i, W1, b1, Wm, bm, W6, b6);
        __syncthreads();
        mm(WB[1], WB[0], ACC[0]);                  // n >= 4 always
        int cur = 0;
        for (int i = 2; i < n; ++i) {
            __syncthreads();
            mm(WB[i], ACC[cur], ACC[cur ^ 1]);
            cur ^= 1;
        }
        __syncthreads();
        store_mat(gP + (size_t)k * MSZ, ACC[cur]);
    }
    grid_barrier(base, 1);

    // ---- Phase B ----
    if (k < NBB) {
        const int lo = k * CHB;
        const int hi = (lo + CHB < NBA) ? lo + CHB : NBA;
        const int n  = hi - lo;                    // 4,4,4,2
        for (int i = 0; i < n; ++i)
            load_mat(WB[i], gP + (size_t)(lo + i) * MSZ);
        __syncthreads();
        mm(WB[1], WB[0], ACC[0]);                  // n >= 2 always
        int cur = 0;
        for (int i = 2; i < n; ++i) {
            __syncthreads();
            mm(WB[i], ACC[cur], ACC[cur ^ 1]);
            cur ^= 1;
        }
        __syncthreads();
        store_mat(gQ + (size_t)k * MSZ, ACC[cur]);
    }
    grid_barrier(base, 2);

    // ---- Phase C ----
    if (k == 0) {
        for (int i = 0; i < NBB; ++i)
            load_mat(WB[i], gQ + (size_t)i * MSZ);
        __syncthreads();
        mm(WB[1], WB[0], ACC[0]);
        int cur = 0;
        for (int i = 2; i < NBB; ++i) {
            __syncthreads();
            mm(WB[i], ACC[cur], ACC[cur ^ 1]);
            cur ^= 1;
        }
        __syncthreads();
        store_mat(gF, ACC[cur]);

        // Flag: is the composed A negligible vs c? (fp32-provable threshold)
        __shared__ int samax;
        if (threadIdx.x == 0) samax = 0;
        __syncthreads();
        float m = 0.f;
        for (int i = threadIdx.x; i < MSZ; i += NT) {
            int r = i / ST, c = i % ST;
            if (r < D && c < D) m = fmaxf(m, fabsf(ACC[cur][i]));
        }
        atomicMax(&samax, __float_as_int(m));   // nonneg floats: int order ok
        __syncthreads();
        if (threadIdx.x == 0)
            gFlag = (__int_as_float(samax) < 1e-12f) ? 1 : 0;
    }
}

// ---------------------------------------------------------------------------
// Output. Fast path (A negligible): stream the repeating 128B pattern `c`
// into out — pure STG.128 write stream. Fallback: full c + A*x (always
// correct). gF holds the composed matrix (row stride ST, c at column 32).
// ---------------------------------------------------------------------------
__global__ void output_kernel(const float* __restrict__ x,
                              float* __restrict__ out,
                              int n4 /* out_size / 4 */) {
    const int tid = blockIdx.x * blockDim.x + threadIdx.x;
    const int nt  = gridDim.x * blockDim.x;   // multiple of 8 by construction
    const int flag = gFlag;

    if (flag) {
        const int slot = tid & 7;
        float4 cv = make_float4(gF[(slot * 4 + 0) * ST + D],
                                gF[(slot * 4 + 1) * ST + D],
                                gF[(slot * 4 + 2) * ST + D],
                                gF[(slot * 4 + 3) * ST + D]);
        float4* o4 = (float4*)out;
        for (int i = tid; i < n4; i += nt) __stcs(&o4[i], cv);
    } else {
        const int n = n4 * 4;
        for (int e = tid; e < n; e += nt) {
            const int b = e >> 5;
            const int i = e & 31;
            const float* xr = x + (size_t)b * D;
            float acc = gF[i * ST + D];          // c[i]
#pragma unroll
            for (int jj = 0; jj < D; ++jj)
                acc = fmaf(gF[i * ST + jj], xr[jj], acc);
            out[e] = acc;
        }
    }
}

// ---------------------------------------------------------------------------
// Launch. Inputs identified by element counts (relative order disambiguates
// W1/W6 and b1/b6).
// ---------------------------------------------------------------------------
extern "C" void kernel_launch(void* const* d_in, const int* in_sizes, int n_in,
                              void* d_out, int out_size) {
    const float *x = 0, *W1 = 0, *b1 = 0, *Wm = 0, *bm = 0, *W6 = 0, *b6 = 0;
    for (int i = 0; i < n_in; ++i) {
        const int s = in_sizes[i];
        const float* p = (const float*)d_in[i];
        if (s == NMID * D * D) {
            Wm = p;
        } else if (s > 100000) {
            x = p;
        } else if (s == NMID * D) {
            bm = p;
        } else if (s == D * D) {
            if (!W1) W1 = p; else W6 = p;
        } else if (s == D) {
            if (!b1) b1 = p; else b6 = p;
        }
    }

    compose_kernel<<<NBA, NT>>>(W1, b1, Wm, bm, W6, b6);

    const int n4 = out_size / 4;
    output_kernel<<<1184, 256>>>(x, (float*)d_out, n4);
}

// round 5
// speedup vs baseline: 2.0000x; 1.1304x over previous
#include <cuda_runtime.h>

#define D 32
#define NMID 80
#define NLAY 82            // total layers
#define ST 36              // padded row stride (floats); cols 0..31=A, 32=c
#define MSZ (D * ST)       // 1152 floats = 4.5 KB per (A|c) tile
#define NBA 14             // phase-A blocks
#define CH  6              // layers per phase-A block (last gets 4)
#define NBB 4              // phase-B blocks
#define NT  288            // 32 rows x 9 col-groups, all threads active

// Global scratch (no allocations allowed).
__device__ __align__(16) float gP[NBA * MSZ];   // phase-A partials
__device__ __align__(16) float gQ[NBB * MSZ];   // phase-B partials
__device__ __align__(16) float gF[MSZ];         // final composed (A|c)
__device__ int gFlag;                            // 1 => A negligible
__device__ unsigned gCount = 0;                  // barrier counter (self-reset)
__device__ volatile unsigned gPhase = 0;         // monotone phase (replay-safe)

// ---------------------------------------------------------------------------
// Grid barrier among NBA co-resident blocks (NBA << SM count). gPhase is
// monotone across graph replays; base captured at entry is uniform because
// no block can pass barrier 1 until all blocks have entered.
// ---------------------------------------------------------------------------
__device__ __forceinline__ void grid_barrier(unsigned base, int it) {
    __syncthreads();
    if (threadIdx.x == 0) {
        __threadfence();
        unsigned c = atomicAdd(&gCount, 1u);
        if (c == NBA - 1u) {
            gCount = 0u;
            __threadfence();
            gPhase = gPhase + 1u;           // single writer (last arriver)
        } else {
            const unsigned tgt = base + (unsigned)it;
            while (gPhase < tgt) { __nanosleep(64); }
        }
        __threadfence();
    }
    __syncthreads();
}

// ---------------------------------------------------------------------------
// Build (W|b) tile in smem, fully vectorized. S is [32 x ST] floats.
// Threads 0..255: A-part (8 float4 per row). Threads 256..287: col 32..35
// (= {b[r],0,0,0}).
// ---------------------------------------------------------------------------
__device__ __forceinline__ void load_aug(float* S, const float* __restrict__ W,
                                         const float* __restrict__ b) {
    const int t = threadIdx.x;
    float4* S4 = (float4*)S;
    if (t < 256) {
        const int r = t >> 3, q = t & 7;
        S4[r * 9 + q] = ((const float4*)W)[r * 8 + q];
    } else {
        const int r = t - 256;
        S4[r * 9 + 8] = make_float4(b[r], 0.f, 0.f, 0.f);
    }
}

// global <-> smem tile copies: exactly one float4 per thread (288 * 4 = 1152).
__device__ __forceinline__ void load_mat(float* S, const float* g) {
    ((float4*)S)[threadIdx.x] = ((const float4*)g)[threadIdx.x];
}
__device__ __forceinline__ void store_mat(float* g, const float* S) {
    ((float4*)g)[threadIdx.x] = ((const float4*)S)[threadIdx.x];
}

// ---------------------------------------------------------------------------
// Affine compose: OUT = L o R  (apply R first):
//   OUT.A = L.A * R.A ; OUT.c = L.A * R.c + L.c
// All tiles [32 x ST] in smem. Thread (r,g) computes OUT[r][4g..4g+3].
// Col group 8 holds c in component .x (R's cols 33..35 are zero).
// Returns the thread's float4; caller stores it.
// ---------------------------------------------------------------------------
__device__ __forceinline__ float4 mm_val(const float* __restrict__ Ls,
                                         const float* __restrict__ Rs,
                                         int r, int g) {
    const float4* L4 = (const float4*)(Ls + r * ST);
    const float4* R4 = (const float4*)Rs;
    float4 a = make_float4(0.f, 0.f, 0.f, 0.f);
#pragma unroll
    for (int k4 = 0; k4 < 8; ++k4) {
        const float4 lv = L4[k4];
        const float4 r0 = R4[(4 * k4 + 0) * 9 + g];
        const float4 r1 = R4[(4 * k4 + 1) * 9 + g];
        const float4 r2 = R4[(4 * k4 + 2) * 9 + g];
        const float4 r3 = R4[(4 * k4 + 3) * 9 + g];
        a.x = fmaf(lv.x, r0.x, a.x); a.y = fmaf(lv.x, r0.y, a.y);
        a.z = fmaf(lv.x, r0.z, a.z); a.w = fmaf(lv.x, r0.w, a.w);
        a.x = fmaf(lv.y, r1.x, a.x); a.y = fmaf(lv.y, r1.y, a.y);
        a.z = fmaf(lv.y, r1.z, a.z); a.w = fmaf(lv.y, r1.w, a.w);
        a.x = fmaf(lv.z, r2.x, a.x); a.y = fmaf(lv.z, r2.y, a.y);
        a.z = fmaf(lv.z, r2.z, a.z); a.w = fmaf(lv.z, r2.w, a.w);
        a.x = fmaf(lv.w, r3.x, a.x); a.y = fmaf(lv.w, r3.y, a.y);
        a.z = fmaf(lv.w, r3.z, a.z); a.w = fmaf(lv.w, r3.w, a.w);
    }
    if (g == 8) a.x += Ls[r * ST + D];     // + L.c
    return a;
}

__device__ __forceinline__ void mm(const float* Ls, const float* Rs,
                                   float* out, int r, int g) {
    float4 a = mm_val(Ls, Rs, r, g);
    ((float4*)out)[r * 9 + g] = a;
}

// Serial right-to-left chain over tiles S[0..n-1] (S[i] = later layer for
// larger i). Uses S[6] then recycles consumed slots. Returns result slot.
__device__ __forceinline__ int chain(float* Sb, int n, int r, int g) {
    // Sb is base of 7 tiles, each MSZ floats.
#define TILE(i) (Sb + (i) * MSZ)
    __syncthreads();
    mm(TILE(1), TILE(0), TILE(6), r, g);
    int prev = 6;
    for (int i = 2; i < n; ++i) {
        __syncthreads();
        mm(TILE(i), TILE(prev == 6 ? 6 : prev), TILE(i - 2), r, g);
        prev = i - 2;
    }
    __syncthreads();
    return prev;
#undef TILE
}

// ---------------------------------------------------------------------------
// Compose the 82 layers into gF with 2 grid barriers.
// Phase A: 14 blocks x <=6 layers. Phase B: 4 blocks combine 14 partials.
// Phase C: block 0 combines 4 -> gF + flag.
// ---------------------------------------------------------------------------
__global__ void __launch_bounds__(NT)
compose_kernel(const float* __restrict__ W1, const float* __restrict__ b1,
               const float* __restrict__ Wm, const float* __restrict__ bm,
               const float* __restrict__ W6, const float* __restrict__ b6) {
    __shared__ __align__(16) float S[7 * MSZ];   // 31.5 KB
    const unsigned base = gPhase;
    const int k = blockIdx.x;
    const int t = threadIdx.x;
    const int r = t / 9, g = t % 9;

    // ---- Phase A ----
    {
        const int lo = k * CH;
        const int hi = (lo + CH < NLAY) ? lo + CH : NLAY;
        const int n  = hi - lo;                   // 6 (last block: 4)
        for (int i = 0; i < n; ++i) {
            const int l = lo + i;
            const float* W; const float* b;
            if (l == 0)             { W = W1; b = b1; }
            else if (l == NLAY - 1) { W = W6; b = b6; }
            else { W = Wm + (size_t)(l - 1) * D * D; b = bm + (l - 1) * D; }
            load_aug(S + i * MSZ, W, b);
        }
        int res = chain(S, n, r, g);
        store_mat(gP + (size_t)k * MSZ, S + res * MSZ);
    }
    grid_barrier(base, 1);

    // ---- Phase B ----
    if (k < NBB) {
        const int lo = k * 4;
        const int hi = (lo + 4 < NBA) ? lo + 4 : NBA;
        const int n  = hi - lo;                   // 4,4,4,2
        for (int i = 0; i < n; ++i)
            load_mat(S + i * MSZ, gP + (size_t)(lo + i) * MSZ);
        int res = chain(S, n, r, g);
        store_mat(gQ + (size_t)k * MSZ, S + res * MSZ);
    }
    grid_barrier(base, 2);

    // ---- Phase C (block 0): combine 4 -> gF, compute flag ----
    if (k == 0) {
        for (int i = 0; i < NBB; ++i)
            load_mat(S + i * MSZ, gQ + (size_t)i * MSZ);
        __syncthreads();
        mm(S + 1 * MSZ, S + 0 * MSZ, S + 6 * MSZ, r, g);   // P1 o P0
        __syncthreads();
        mm(S + 2 * MSZ, S + 6 * MSZ, S + 0 * MSZ, r, g);   // P2 o ...
        __syncthreads();
        // Final: P3 o ... -> write gF directly, fold |A| max.
        float4 a = mm_val(S + 3 * MSZ, S + 0 * MSZ, r, g);
        ((float4*)gF)[r * 9 + g] = a;

        float m = 0.f;
        if (g < 8) {   // A columns only (g==8 is c / padding)
            m = fmaxf(fmaxf(fabsf(a.x), fabsf(a.y)),
                      fmaxf(fabsf(a.z), fabsf(a.w)));
        }
        __shared__ int samax;
        if (t == 0) samax = 0;
        __syncthreads();
#pragma unroll
        for (int o = 16; o > 0; o >>= 1)
            m = fmaxf(m, __shfl_xor_sync(0xffffffffu, m, o));
        if ((t & 31) == 0) atomicMax(&samax, __float_as_int(m));
        __syncthreads();
        if (t == 0)
            gFlag = (__int_as_float(samax) < 1e-12f) ? 1 : 0;
    }
}

// ---------------------------------------------------------------------------
// Output. Fast path (A negligible): stream repeating 128B pattern c.
// Fallback: out[b][i] = c[i] + sum_j A[i][j]*x[b][j] (always correct).
// gF layout: A[i][j] = gF[i*ST+j], c[i] = gF[i*ST+32].
// ---------------------------------------------------------------------------
__global__ void output_kernel(const float* __restrict__ x,
                              float* __restrict__ out,
                              int n4 /* out_size / 4 */) {
    const int tid = blockIdx.x * blockDim.x + threadIdx.x;
    const int nt  = gridDim.x * blockDim.x;   // multiple of 8
    const int flag = gFlag;

    if (flag) {
        const int slot = tid & 7;
        float4 cv = make_float4(gF[(slot * 4 + 0) * ST + D],
                                gF[(slot * 4 + 1) * ST + D],
                                gF[(slot * 4 + 2) * ST + D],
                                gF[(slot * 4 + 3) * ST + D]);
        float4* o4 = (float4*)out;
        for (int i = tid; i < n4; i += nt) __stcs(&o4[i], cv);
    } else {
        const int n = n4 * 4;
        for (int e = tid; e < n; e += nt) {
            const int b = e >> 5;
            const int i = e & 31;
            const float* xr = x + (size_t)b * D;
            float acc = gF[i * ST + D];
#pragma unroll
            for (int jj = 0; jj < D; ++jj)
                acc = fmaf(gF[i * ST + jj], xr[jj], acc);
            out[e] = acc;
        }
    }
}

// ---------------------------------------------------------------------------
// Launch. Inputs identified by element counts (relative order disambiguates
// W1/W6 and b1/b6).
// ---------------------------------------------------------------------------
extern "C" void kernel_launch(void* const* d_in, const int* in_sizes, int n_in,
                              void* d_out, int out_size) {
    const float *x = 0, *W1 = 0, *b1 = 0, *Wm = 0, *bm = 0, *W6 = 0, *b6 = 0;
    for (int i = 0; i < n_in; ++i) {
        const int s = in_sizes[i];
        const float* p = (const float*)d_in[i];
        if (s == NMID * D * D) {
            Wm = p;
        } else if (s > 100000) {
            x = p;
        } else if (s == NMID * D) {
            bm = p;
        } else if (s == D * D) {
            if (!W1) W1 = p; else W6 = p;
        } else if (s == D) {
            if (!b1) b1 = p; else b6 = p;
        }
    }

    compose_kernel<<<NBA, NT>>>(W1, b1, Wm, bm, W6, b6);

    const int n4 = out_size / 4;
    output_kernel<<<1184, 256>>>(x, (float*)d_out, n4);
}